// round 17
// baseline (speedup 1.0000x reference)
#include <cuda_runtime.h>
#include <cuda_fp16.h>

// Problem constants
#define NB 2
#define NS 2048
#define NE 1024
#define NH 16
#define NHD 64
#define NM (NB * NS)      // 4096
#define NQKV (3 * NE)     // 3072

// Scratch (allocation-free rule: __device__ globals). All fp16.
__device__ __half g_qkv[(size_t)NM * NQKV];    // 24 MB
__device__ __half g_ctx[(size_t)NM * NE];      // 8 MB
__device__ __half g_xt[(size_t)NM * NE];       // 8 MB
__device__ __half g_wqkvt[(size_t)NQKV * NE];  // 6 MB
__device__ __half g_wot[(size_t)NE * NE];      // 2 MB

// ---------------------------------------------------------------------------
// helpers
// ---------------------------------------------------------------------------
__device__ __forceinline__ void mma_f16(float* d, const unsigned* a,
                                        const unsigned* b, const float* c) {
    asm volatile(
        "mma.sync.aligned.m16n8k16.row.col.f32.f16.f16.f32 "
        "{%0,%1,%2,%3}, {%4,%5,%6,%7}, {%8,%9}, {%10,%11,%12,%13};"
        : "=f"(d[0]), "=f"(d[1]), "=f"(d[2]), "=f"(d[3])
        : "r"(a[0]), "r"(a[1]), "r"(a[2]), "r"(a[3]),
          "r"(b[0]), "r"(b[1]),
          "f"(c[0]), "f"(c[1]), "f"(c[2]), "f"(c[3]));
}

#define LDSM4(r, addr) \
    asm volatile("ldmatrix.sync.aligned.m8n8.x4.shared.b16 " \
                 "{%0,%1,%2,%3}, [%4];" \
                 : "=r"((r)[0]), "=r"((r)[1]), "=r"((r)[2]), "=r"((r)[3]) \
                 : "r"(addr))
#define LDSM4T(r, addr) \
    asm volatile("ldmatrix.sync.aligned.m8n8.x4.trans.shared.b16 " \
                 "{%0,%1,%2,%3}, [%4];" \
                 : "=r"((r)[0]), "=r"((r)[1]), "=r"((r)[2]), "=r"((r)[3]) \
                 : "r"(addr))

__device__ __forceinline__ unsigned sptr(const void* p) {
    return (unsigned)__cvta_generic_to_shared(p);
}
#define CP16(dst_s, src_g) \
    asm volatile("cp.async.cg.shared.global [%0], [%1], 16;" \
                 :: "r"(dst_s), "l"(src_g))

// mbarrier ops
#define MBAR_INIT(addr, cnt) \
    asm volatile("mbarrier.init.shared.b64 [%0], %1;" \
                 :: "r"(addr), "r"(cnt) : "memory")
#define MBAR_ARRIVE(addr) \
    asm volatile("mbarrier.arrive.shared::cta.b64 _, [%0];" \
                 :: "r"(addr) : "memory")
#define CP_MBAR_ARRIVE(addr) \
    asm volatile("cp.async.mbarrier.arrive.noinc.shared::cta.b64 [%0];" \
                 :: "r"(addr) : "memory")
#define MBAR_WAIT_PAR(addr, ph) do { \
    unsigned _d = 0; \
    while (!_d) { \
        asm volatile("{\n\t.reg .pred p;\n\t" \
            "mbarrier.try_wait.parity.acquire.cta.shared::cta.b64 p, [%1], %2, 0x989680;\n\t" \
            "selp.b32 %0, 1, 0, p;\n\t}" \
            : "=r"(_d) : "r"(addr), "r"(ph) : "memory"); \
    } \
} while (0)

__device__ __forceinline__ unsigned packh2(float lo, float hi) {
    __half2 h = __floats2half2_rn(lo, hi);
    return *reinterpret_cast<unsigned*>(&h);
}

__device__ __forceinline__ unsigned exp2_h2(float t0, float t1) {
    unsigned u = packh2(t0, t1);
    asm("ex2.approx.f16x2 %0, %1;" : "=r"(u) : "r"(u));
    return u;
}

// ---------------------------------------------------------------------------
// Merged elementwise fp32 -> fp16 for x, W_qkv, W_out (one launch)
// ---------------------------------------------------------------------------
#define NX4 ((NM * NE) / 8)
#define NW4 ((NQKV * NE) / 8)
#define NO4 ((NE * NE) / 8)
#define NCVT (NX4 + NW4 + NO4)

__global__ __launch_bounds__(256) void cvt_all(
    const float4* __restrict__ x,  const float4* __restrict__ wq,
    const float4* __restrict__ wo,
    uint4* __restrict__ xt, uint4* __restrict__ wqt, uint4* __restrict__ wot)
{
    int i = blockIdx.x * 256 + threadIdx.x;
    const float4* src;
    uint4* dst;
    int j;
    if (i < NX4)            { j = i;              src = x;  dst = xt;  }
    else if (i < NX4 + NW4) { j = i - NX4;        src = wq; dst = wqt; }
    else                    { j = i - NX4 - NW4;  src = wo; dst = wot; }
    float4 v0 = src[j * 2];
    float4 v1 = src[j * 2 + 1];
    uint4 u;
    u.x = packh2(v0.x, v0.y);
    u.y = packh2(v0.z, v0.w);
    u.z = packh2(v1.x, v1.y);
    u.w = packh2(v1.z, v1.w);
    dst[j] = u;
}

// ---------------------------------------------------------------------------
// FP16 NT GEMM + bias, decoupled ring-3 mbarrier pipeline (round-15 proven).
// 128x128 CTA tile, BK=64, 256 threads, warp grid 2x4, warp tile 64x32,
// paired-x4 W fragments, __launch_bounds__(256,2).
// ---------------------------------------------------------------------------
#define GBUF 18432                           // 128 * 144 bytes
#define GA_B  0                              // A bufs [3]
#define GW_B  (3 * GBUF)                     // W bufs [3]
#define GMB_B (6 * GBUF)                     // mbarriers: full[3], empty[3]
#define GEMM_SMEM_BYTES (6 * GBUF + 128)     // 110720

template <int OUT>
__global__ __launch_bounds__(256, 2) void gemm_h(
    const __half* __restrict__ A, const __half* __restrict__ W,
    const float* __restrict__ bias, void* __restrict__ Cv,
    int Mdim, int Ndim, int Kdim)
{
    extern __shared__ __align__(16) char smg[];
    const unsigned smem_u = sptr(smg);

    const int tid  = threadIdx.x;
    const int wid  = tid >> 5;
    const int lane = tid & 31;
    const int mg   = wid >> 2;
    const int ng   = wid & 3;
    const int bm   = blockIdx.y * 128;
    const int bn   = blockIdx.x * 128;
    const int lq   = lane >> 2;
    const int lr   = lane & 3;
    const int NT   = Kdim / 64;

    const unsigned offA = (mg * 64 + (lane & 15)) * 144 + (lane >> 4) * 16;
    const unsigned offW4 = (ng * 32 + ((lane >> 4) << 3) + (lane & 7)) * 144
                         + ((lane >> 3) & 1) * 16;

    const unsigned mb_full  = smem_u + GMB_B;        // 3 x 8B
    const unsigned mb_empty = smem_u + GMB_B + 24;   // 3 x 8B

    if (tid == 0) {
        #pragma unroll
        for (int j = 0; j < 3; j++) {
            MBAR_INIT(mb_full + j * 8, 256);
            MBAR_INIT(mb_empty + j * 8, 256);
        }
    }
    __syncthreads();

    float acc[4][4][4] = {};

    auto fill = [&](int t) {
        const int bf = t % 3;
        const unsigned ad = smem_u + GA_B + bf * GBUF;
        const unsigned wd = smem_u + GW_B + bf * GBUF;
        const int kt = t * 64;
        #pragma unroll
        for (int i = 0; i < 4; i++) {
            int idx = i * 256 + tid;
            int row = idx >> 3;
            int seg = idx & 7;
            CP16(ad + row * 144 + seg * 16,
                 A + (size_t)(bm + row) * Kdim + kt + seg * 8);
            CP16(wd + row * 144 + seg * 16,
                 W + (size_t)(bn + row) * Kdim + kt + seg * 8);
        }
        CP_MBAR_ARRIVE(mb_full + bf * 8);
    };

    fill(0);
    fill(1);

    for (int t = 0; t < NT; t++) {
        const int bf = t % 3;

        {
            int u = t + 2;
            if (u < NT) {
                if (u >= 3)
                    MBAR_WAIT_PAR(mb_empty + (u % 3) * 8, (u / 3 - 1) & 1);
                fill(u);
            }
        }

        MBAR_WAIT_PAR(mb_full + bf * 8, (t / 3) & 1);

        const unsigned abase = smem_u + GA_B + bf * GBUF + offA;
        const unsigned wbase = smem_u + GW_B + bf * GBUF + offW4;
        #pragma unroll
        for (int kc = 0; kc < 4; kc++) {
            unsigned a[4][4], b4[2][4];
            #pragma unroll
            for (int mt = 0; mt < 4; mt++)
                LDSM4(a[mt], abase + mt * 2304 + kc * 32);
            #pragma unroll
            for (int p = 0; p < 2; p++)
                LDSM4(b4[p], wbase + p * 2304 + kc * 32);
            #pragma unroll
            for (int mt = 0; mt < 4; mt++)
                #pragma unroll
                for (int nt = 0; nt < 4; nt++)
                    mma_f16(acc[mt][nt], a[mt],
                            &b4[nt >> 1][(nt & 1) * 2], acc[mt][nt]);
        }

        MBAR_ARRIVE(mb_empty + bf * 8);
    }

    #pragma unroll
    for (int mt = 0; mt < 4; mt++) {
        int r0 = bm + mg * 64 + mt * 16 + lq;
        #pragma unroll
        for (int nt = 0; nt < 4; nt++) {
            int col = bn + ng * 32 + nt * 8 + lr * 2;
            float2 bv = *(const float2*)&bias[col];
            float v00 = acc[mt][nt][0] + bv.x;
            float v01 = acc[mt][nt][1] + bv.y;
            float v10 = acc[mt][nt][2] + bv.x;
            float v11 = acc[mt][nt][3] + bv.y;
            if (OUT == 2) {
                __half* C = (__half*)Cv;
                *(unsigned*)&C[(size_t)r0 * Ndim + col]       = packh2(v00, v01);
                *(unsigned*)&C[(size_t)(r0 + 8) * Ndim + col] = packh2(v10, v11);
            } else {
                float* C = (float*)Cv;
                *(float2*)&C[(size_t)r0 * Ndim + col]       = make_float2(v00, v01);
                *(float2*)&C[(size_t)(r0 + 8) * Ndim + col] = make_float2(v10, v11);
            }
        }
    }
}

// ---------------------------------------------------------------------------
// Flash attention v6: split K/V barrier pipelines.
// 2 CTAs/SM, 256 threads = 8 warps, warp grid 4(m) x 2(n), warp tile
// 16 q-rows x 64 keys, K/V rings of 2, hoisted Q frags.
// K buffer is released right after QK and refilled BEFORE softmax;
// fullV wait deferred to just before PV. Finer-grained overlap.
// ---------------------------------------------------------------------------
#define AQ_B   0                       // Q [64][72] fp16 = 9216 B
#define AK_B   9216                    // K [2][128][72] = 36864 B
#define AV_B   46080                   // V [2][128][72] = 36864 B
#define ARM_B  82944                   // m float [2][64]
#define ARS_B  83456                   // l float [2][64]
#define AMB_B  83968                   // mbarriers: fullK[2] emptyK[2] fullV[2] emptyV[2]
#define ATTN_SMEM_BYTES 84160
#define ATHREADS 256
#define NTILES (NS / 128)              // 16 key tiles
#define L2E 1.44269504f

__global__ __launch_bounds__(ATHREADS, 2) void attn_f16(
    const __half* __restrict__ qkv, __half* __restrict__ ctx)
{
    extern __shared__ __align__(16) char smc[];
    const unsigned smem_u = sptr(smc);
    __half* Qs = (__half*)(smc + AQ_B);

    const int tid  = threadIdx.x;
    const int wid  = tid >> 5;
    const int lane = tid & 31;
    const int mg   = wid >> 1;
    const int ng   = wid & 1;
    const int lq   = lane >> 2;
    const int lr   = lane & 3;
    const int q0   = blockIdx.x * 64;
    const int h    = blockIdx.y;
    const int b    = blockIdx.z;

    const __half* base  = qkv + (size_t)b * NS * NQKV + h * (3 * NHD);
    const __half* kbase = base + NHD;
    const __half* vbase = base + 2 * NHD;

    const unsigned offQ  = AQ_B + (mg * 16 + (lane & 15)) * 144 + (lane >> 4) * 16;
    const unsigned offK4 = (ng * 64 + ((lane >> 4) << 3) + (lane & 7)) * 144
                         + ((lane >> 3) & 1) * 16;
    const unsigned offV  = (ng * 64 + (lane & 15)) * 144 + (lane >> 4) * 16;

    const unsigned mbFK = smem_u + AMB_B;        // fullK[2]
    const unsigned mbEK = smem_u + AMB_B + 16;   // emptyK[2]
    const unsigned mbFV = smem_u + AMB_B + 32;   // fullV[2]
    const unsigned mbEV = smem_u + AMB_B + 48;   // emptyV[2]

    if (tid == 0) {
        #pragma unroll
        for (int j = 0; j < 2; j++) {
            MBAR_INIT(mbFK + j * 8, ATHREADS);
            MBAR_INIT(mbEK + j * 8, ATHREADS);
            MBAR_INIT(mbFV + j * 8, ATHREADS);
            MBAR_INIT(mbEV + j * 8, ATHREADS);
        }
    }
    __syncthreads();

    auto fillK = [&](int t) {
        const int bf = t & 1;
        const unsigned kd = smem_u + AK_B + bf * 18432;
        #pragma unroll
        for (int i = 0; i < 4; i++) {
            int idx = i * ATHREADS + tid;
            int row = idx >> 3;
            int seg = idx & 7;
            CP16(kd + row * 144 + seg * 16,
                 kbase + (size_t)(t * 128 + row) * NQKV + seg * 8);
        }
        CP_MBAR_ARRIVE(mbFK + bf * 8);
    };
    auto fillV = [&](int t) {
        const int bf = t & 1;
        const unsigned vd = smem_u + AV_B + bf * 18432;
        #pragma unroll
        for (int i = 0; i < 4; i++) {
            int idx = i * ATHREADS + tid;
            int row = idx >> 3;
            int seg = idx & 7;
            CP16(vd + row * 144 + seg * 16,
                 vbase + (size_t)(t * 128 + row) * NQKV + seg * 8);
        }
        CP_MBAR_ARRIVE(mbFV + bf * 8);
    };

    fillK(0);
    fillV(0);
    fillK(1);
    fillV(1);

    // Q fill with 0.125 scale (exact in fp16)
    {
        const __half2 sc = __floats2half2_rn(0.125f, 0.125f);
        #pragma unroll
        for (int i = 0; i < 2; i++) {
            int idx = i * ATHREADS + tid;
            int row = idx >> 3;
            int seg = idx & 7;
            uint4 v = *(const uint4*)(base + (size_t)(q0 + row) * NQKV + seg * 8);
            __half2* p = (__half2*)&v;
            p[0] = __hmul2(p[0], sc);
            p[1] = __hmul2(p[1], sc);
            p[2] = __hmul2(p[2], sc);
            p[3] = __hmul2(p[3], sc);
            *(uint4*)(Qs + row * 72 + seg * 8) = v;
        }
    }
    __syncthreads();   // Q visible

    unsigned aq[4][4];
    {
        const unsigned qb = smem_u + offQ;
        #pragma unroll
        for (int kc = 0; kc < 4; kc++)
            LDSM4(aq[kc], qb + kc * 32);
    }

    float o[8][4] = {};
    float m_run[2] = {-1e30f, -1e30f};
    float l_run[2] = {0.f, 0.f};

    for (int t = 0; t < NTILES; t++) {
        const int bf = t & 1;
        const int ph = (t >> 1) & 1;

        // ---- QK^T: wait K, compute, release + refill K early ----
        MBAR_WAIT_PAR(mbFK + bf * 8, ph);

        const unsigned kb = smem_u + AK_B + bf * 18432 + offK4;

        float s[8][4] = {};
        #pragma unroll
        for (int kc = 0; kc < 4; kc++) {
            unsigned kf[4][4];
            #pragma unroll
            for (int p = 0; p < 4; p++)
                LDSM4(kf[p], kb + p * 2304 + kc * 32);
            #pragma unroll
            for (int nt = 0; nt < 8; nt++)
                mma_f16(s[nt], aq[kc],
                        &kf[nt >> 1][(nt & 1) * 2], s[nt]);
        }

        MBAR_ARRIVE(mbEK + bf * 8);
        if (t + 2 < NTILES) {
            MBAR_WAIT_PAR(mbEK + bf * 8, ph);
            fillK(t + 2);
        }

        // ---- softmax: max + fp16x2 exp2 -> packed P frags; ALU row sum ----
        unsigned pf[8][2];
        #pragma unroll
        for (int hf = 0; hf < 2; hf++) {
            float v = -1e30f;
            #pragma unroll
            for (int nt = 0; nt < 8; nt++) {
                v = fmaxf(v, s[nt][hf * 2 + 0]);
                v = fmaxf(v, s[nt][hf * 2 + 1]);
            }
            v = fmaxf(v, __shfl_xor_sync(0xffffffffu, v, 1));
            v = fmaxf(v, __shfl_xor_sync(0xffffffffu, v, 2));
            float m_new = fmaxf(m_run[hf], v);
            float corr  = __expf(m_run[hf] - m_new);
            m_run[hf] = m_new;
            float mb = m_new * L2E;
            float rs = 0.f;
            #pragma unroll
            for (int nt = 0; nt < 8; nt++) {
                float t0 = fmaf(s[nt][hf * 2 + 0], L2E, -mb);
                float t1 = fmaf(s[nt][hf * 2 + 1], L2E, -mb);
                unsigned pp = exp2_h2(t0, t1);
                pf[nt][hf] = pp;
                float2 f = __half22float2(*reinterpret_cast<__half2*>(&pp));
                rs += f.x + f.y;
            }
            rs += __shfl_xor_sync(0xffffffffu, rs, 1);
            rs += __shfl_xor_sync(0xffffffffu, rs, 2);
            l_run[hf] = l_run[hf] * corr + rs;
            #pragma unroll
            for (int nt = 0; nt < 8; nt++) {
                o[nt][hf * 2 + 0] *= corr;
                o[nt][hf * 2 + 1] *= corr;
            }
        }

        // ---- PV: wait V (deferred), compute, release + refill V ----
        MBAR_WAIT_PAR(mbFV + bf * 8, ph);

        const unsigned vb = smem_u + AV_B + bf * 18432 + offV;
        #pragma unroll
        for (int kc = 0; kc < 4; kc++) {
            unsigned a[4];
            a[0] = pf[2 * kc + 0][0];
            a[1] = pf[2 * kc + 0][1];
            a[2] = pf[2 * kc + 1][0];
            a[3] = pf[2 * kc + 1][1];
            #pragma unroll
            for (int np = 0; np < 4; np++) {
                unsigned vf[4];
                LDSM4T(vf, vb + kc * 2304 + np * 32);
                mma_f16(o[2 * np + 0], a, &vf[0], o[2 * np + 0]);
                mma_f16(o[2 * np + 1], a, &vf[2], o[2 * np + 1]);
            }
        }

        MBAR_ARRIVE(mbEV + bf * 8);
        if (t + 2 < NTILES) {
            MBAR_WAIT_PAR(mbEV + bf * 8, ph);
            fillV(t + 2);
        }
    }

    // ---- epilogue: merge the two key-slices, normalize, store fp16 ctx ----
    __syncthreads();
    float* rm = (float*)(smc + ARM_B);   // [ng][64]
    float* rl = (float*)(smc + ARS_B);
    if (lr == 0) {
        int r = mg * 16 + lq;
        rm[ng * 64 + r]     = m_run[0];
        rm[ng * 64 + r + 8] = m_run[1];
        rl[ng * 64 + r]     = l_run[0];
        rl[ng * 64 + r + 8] = l_run[1];
    }
    __syncthreads();

    float fsc[2], linv[2];
    #pragma unroll
    for (int hf = 0; hf < 2; hf++) {
        int row = mg * 16 + hf * 8 + lq;
        float m0 = rm[row], m1 = rm[64 + row];
        float m_tot = fmaxf(m0, m1);
        float l_tot = rl[row] * __expf(m0 - m_tot)
                    + rl[64 + row] * __expf(m1 - m_tot);
        fsc[hf]  = __expf(m_run[hf] - m_tot);
        linv[hf] = 1.0f / l_tot;
    }

    float* Os = (float*)(smc + AK_B);    // [64][68] floats, aliases K buf0
    if (ng == 1) {
        int r = mg * 16 + lq;
        #pragma unroll
        for (int nt = 0; nt < 8; nt++) {
            int d = nt * 8 + lr * 2;
            *(float2*)&Os[r * 68 + d] =
                make_float2(o[nt][0] * fsc[0], o[nt][1] * fsc[0]);
            *(float2*)&Os[(r + 8) * 68 + d] =
                make_float2(o[nt][2] * fsc[1], o[nt][3] * fsc[1]);
        }
    }
    __syncthreads();
    if (ng == 0) {
        int r = mg * 16 + lq;
        #pragma unroll
        for (int nt = 0; nt < 8; nt++) {
            int d = nt * 8 + lr * 2;
            float2 p0 = *(const float2*)&Os[r * 68 + d];
            float2 p1 = *(const float2*)&Os[(r + 8) * 68 + d];
            unsigned u0 = packh2((o[nt][0] * fsc[0] + p0.x) * linv[0],
                                 (o[nt][1] * fsc[0] + p0.y) * linv[0]);
            unsigned u1 = packh2((o[nt][2] * fsc[1] + p1.x) * linv[1],
                                 (o[nt][3] * fsc[1] + p1.y) * linv[1]);
            size_t g0 = ((size_t)b * NS + q0 + r) * NE + h * NHD + d;
            size_t g1 = ((size_t)b * NS + q0 + r + 8) * NE + h * NHD + d;
            *(unsigned*)&ctx[g0] = u0;
            *(unsigned*)&ctx[g1] = u1;
        }
    }
}

// ---------------------------------------------------------------------------
extern "C" void kernel_launch(void* const* d_in, const int* in_sizes, int n_in,
                              void* d_out, int out_size)
{
    const float* x     = (const float*)d_in[0];
    const float* W_qkv = (const float*)d_in[1];
    const float* b_qkv = (const float*)d_in[2];
    const float* W_out = (const float*)d_in[3];
    const float* b_out = (const float*)d_in[4];
    float* out = (float*)d_out;

    __half *qkv, *ctx, *xt, *wqkvt, *wot;
    cudaGetSymbolAddress((void**)&qkv,   g_qkv);
    cudaGetSymbolAddress((void**)&ctx,   g_ctx);
    cudaGetSymbolAddress((void**)&xt,    g_xt);
    cudaGetSymbolAddress((void**)&wqkvt, g_wqkvt);
    cudaGetSymbolAddress((void**)&wot,   g_wot);

    cudaFuncSetAttribute(gemm_h<2>,
                         cudaFuncAttributeMaxDynamicSharedMemorySize,
                         GEMM_SMEM_BYTES);
    cudaFuncSetAttribute(gemm_h<0>,
                         cudaFuncAttributeMaxDynamicSharedMemorySize,
                         GEMM_SMEM_BYTES);
    cudaFuncSetAttribute(attn_f16,
                         cudaFuncAttributeMaxDynamicSharedMemorySize,
                         ATTN_SMEM_BYTES);

    // 0) pre-convert inputs to fp16 (single merged launch)
    cvt_all<<<NCVT / 256, 256>>>((const float4*)x, (const float4*)W_qkv,
                                 (const float4*)W_out,
                                 (uint4*)xt, (uint4*)wqkvt, (uint4*)wot);

    // 1) QKV projection (fp16 math, fp32 accum, fp16 out)
    dim3 g1(NQKV / 128, NM / 128);
    gemm_h<2><<<g1, 256, GEMM_SMEM_BYTES>>>(xt, wqkvt, b_qkv, qkv,
                                            NM, NQKV, NE);

    // 2) Flash attention (fp16 tensor cores, split K/V pipelines)
    dim3 g2(NS / 64, NH, NB);
    attn_f16<<<g2, ATHREADS, ATTN_SMEM_BYTES>>>(qkv, ctx);

    // 3) Output projection (fp16 math, fp32 accum, fp32 out)
    dim3 g3(NE / 128, NM / 128);
    gemm_h<0><<<g3, 256, GEMM_SMEM_BYTES>>>(ctx, wot, b_out, out,
                                            NM, NE, NE);
}